// round 6
// baseline (speedup 1.0000x reference)
#include <cuda_runtime.h>

#define N_NODES 50000
#define N_EDGES 800000
#define IN_C 64
#define HID_C 128
#define OUT_C 64
#define SCAN_BLOCKS 196   // 196*256 = 50176 >= N_NODES

// ---------------- scratch (static device globals; no allocation) ----------------
__device__ float g_Sx[N_NODES * IN_C];    // sum_{src->d} x[src]
__device__ float g_h [N_NODES * HID_C];   // hidden activations
__device__ float g_z  [N_NODES * OUT_C];  // z = h @ Wj2
__device__ float g_Szz[N_NODES * OUT_C];  // z_self + sum_src z[src]
__device__ float g_deg[N_NODES];          // in-degree
__device__ float g_se [N_NODES];          // sum of edge_attr per dst
__device__ int   g_cnt[N_NODES];          // histogram counts
__device__ int   g_rp [N_NODES];          // CSR row pointer
__device__ int   g_cur[N_NODES];          // fill cursors
__device__ int   g_bs [256];              // block sums for 2-level scan
__device__ int   g_srcs[N_EDGES];         // CSR column (src) indices
__device__ int   g_any;                   // != 0 -> edge_index is int32

// ---------------- f32x2 packed helpers ----------------
__device__ __forceinline__ void ffma2(unsigned long long& acc,
                                      unsigned long long a, unsigned long long b) {
    asm("fma.rn.f32x2 %0, %1, %2, %0;" : "+l"(acc) : "l"(a), "l"(b));
}
__device__ __forceinline__ unsigned long long f2ull(float a, float b) {
    unsigned long long u;
    asm("mov.b64 %0, {%1, %2};" : "=l"(u) : "f"(a), "f"(b));
    return u;
}
__device__ __forceinline__ float2 ull2f2(unsigned long long u) {
    float2 f;
    asm("mov.b64 {%0, %1}, %2;" : "=f"(f.x), "=f"(f.y) : "l"(u));
    return f;
}

// ---------------- zero small scratch + dtype detect ----------------
__global__ void zero_kernel(const int* __restrict__ ei32) {
    int i = blockIdx.x * blockDim.x + threadIdx.x;
    int stride = gridDim.x * blockDim.x;
    for (int k = i; k < N_NODES; k += stride) { g_cnt[k] = 0; g_se[k] = 0.f; }
    if (blockIdx.x == 0) {
        if (threadIdx.x == 0) g_any = 0;
        __syncthreads();
        int v = 0;
        for (int k = threadIdx.x; k < 1024; k += blockDim.x) v |= ei32[2 * k + 1];
        if (v) atomicOr(&g_any, 1);
    }
}

__device__ __forceinline__ void load_edge(const void* ei, int e, bool is64,
                                          int& src, int& dst) {
    if (is64) {
        const long long* p = (const long long*)ei;
        src = (int)__ldg(p + e); dst = (int)__ldg(p + N_EDGES + e);
    } else {
        const int* p = (const int*)ei;
        src = __ldg(p + e); dst = __ldg(p + N_EDGES + e);
    }
}

// ---------------- CSR build ----------------
__global__ __launch_bounds__(256) void hist_kernel(const void* __restrict__ ei,
                                                   const float* __restrict__ ea) {
    int e = blockIdx.x * blockDim.x + threadIdx.x;
    if (e >= N_EDGES) return;
    bool is64 = (g_any == 0);
    int src, dst;
    load_edge(ei, e, is64, src, dst);
    atomicAdd(&g_cnt[dst], 1);
    atomicAdd(&g_se[dst], __ldg(ea + e));
}

__global__ __launch_bounds__(256) void scan1_kernel() {
    __shared__ int s[256];
    int t = threadIdx.x;
    int i = blockIdx.x * 256 + t;
    int c = (i < N_NODES) ? g_cnt[i] : 0;
    s[t] = c;
    __syncthreads();
    for (int o = 1; o < 256; o <<= 1) {
        int v = (t >= o) ? s[t - o] : 0;
        __syncthreads();
        s[t] += v;
        __syncthreads();
    }
    if (i < N_NODES) g_rp[i] = s[t] - c;
    if (t == 255) g_bs[blockIdx.x] = s[255];
}

__global__ __launch_bounds__(256) void scan2_kernel() {
    __shared__ int s[256];
    int t = threadIdx.x;
    int c = (t < SCAN_BLOCKS) ? g_bs[t] : 0;
    s[t] = c;
    __syncthreads();
    for (int o = 1; o < 256; o <<= 1) {
        int v = (t >= o) ? s[t - o] : 0;
        __syncthreads();
        s[t] += v;
        __syncthreads();
    }
    if (t < SCAN_BLOCKS) g_bs[t] = s[t] - c;
}

__global__ __launch_bounds__(256) void scan3_kernel() {
    int i = blockIdx.x * 256 + threadIdx.x;
    if (i >= N_NODES) return;
    int rp = g_rp[i] + g_bs[i >> 8];
    g_rp[i] = rp;
    g_cur[i] = rp;
    g_deg[i] = (float)g_cnt[i];
}

__global__ __launch_bounds__(256) void fill_kernel(const void* __restrict__ ei) {
    int e = blockIdx.x * blockDim.x + threadIdx.x;
    if (e >= N_EDGES) return;
    bool is64 = (g_any == 0);
    int src, dst;
    load_edge(ei, e, is64, src, dst);
    int p = atomicAdd(&g_cur[dst], 1);
    g_srcs[p] = src;
}

// ---------------- pull layer 1: 16 threads per dst, 64 ch as float4 ----------
__global__ __launch_bounds__(256) void pull1_kernel(const float* __restrict__ x) {
    int tid = blockIdx.x * blockDim.x + threadIdx.x;
    int d = tid >> 4, c = tid & 15;
    if (d >= N_NODES) return;
    int beg = g_rp[d];
    int end = beg + g_cnt[d];
    float4 acc = make_float4(0.f, 0.f, 0.f, 0.f);
#pragma unroll 4
    for (int j = beg; j < end; j++) {
        int s = __ldg(&g_srcs[j]);
        float4 v = __ldg((const float4*)x + s * (IN_C / 4) + c);
        acc.x += v.x; acc.y += v.y; acc.z += v.z; acc.w += v.w;
    }
    ((float4*)g_Sx)[d * (IN_C / 4) + c] = acc;
}

// ---------------- pull layer 2 (z): Szz[d] = z[d] + sum_src z[src] -----------
__global__ __launch_bounds__(256) void pull2z_kernel() {
    int tid = blockIdx.x * blockDim.x + threadIdx.x;
    int d = tid >> 4, c = tid & 15;
    if (d >= N_NODES) return;
    int beg = g_rp[d];
    int end = beg + g_cnt[d];
    float4 acc = __ldg((const float4*)g_z + d * (OUT_C / 4) + c);  // self
#pragma unroll 4
    for (int j = beg; j < end; j++) {
        int s = __ldg(&g_srcs[j]);
        float4 v = __ldg((const float4*)g_z + s * (OUT_C / 4) + c);
        acc.x += v.x; acc.y += v.y; acc.z += v.z; acc.w += v.w;
    }
    ((float4*)g_Szz)[d * (OUT_C / 4) + c] = acc;
}

// ==================== dense layer 1 (unchanged) ====================
// h = relu( v @ W1 + degp1*b1 ), v = [degp1*x (64), Sx+x (64), se (1)]
#define D1_N 32
__global__ __launch_bounds__(256) void dense1_kernel(
    const float* __restrict__ x, const float* __restrict__ W1,
    const float* __restrict__ b1) {
    extern __shared__ float sm[];
    float* Ws = sm;                      // 129*128 = 16512
    float* bs = Ws + 16512;              // 128
    float* dg = bs + 128;                // 32
    float* sep = dg + 32;                // 32 (pad)
    unsigned long long* vsd = (unsigned long long*)(sep + 32); // 32 x 130 ull
    int tid = threadIdx.x;
    int warp = tid >> 5, lane = tid & 31;
    int c4 = lane * 4;
    for (int i = tid; i < 16512; i += 256) Ws[i] = W1[i];
    if (tid < 128) bs[tid] = b1[tid];

    int iters = (N_NODES + D1_N - 1) / D1_N;
    for (int it = blockIdx.x; it < iters; it += gridDim.x) {
        int base = it * D1_N;
        __syncthreads();
        if (tid < D1_N) {
            int gn = base + tid;
            bool ok = gn < N_NODES;
            dg[tid] = ok ? g_deg[gn] + 1.0f : 1.0f;
            float s = ok ? g_se[gn] : 0.0f;
            vsd[tid * 130 + 128] = f2ull(s, s);
        }
        __syncthreads();
        for (int idx = tid; idx < D1_N * 64; idx += 256) {
            int n = idx >> 6, k = idx & 63;
            int gn = base + n;
            float xv = 0.f, sv = 0.f;
            if (gn < N_NODES) { xv = x[gn * 64 + k]; sv = g_Sx[gn * 64 + k]; }
            float a = dg[n] * xv;
            float b = sv + xv;
            vsd[n * 130 + k]      = f2ull(a, a);
            vsd[n * 130 + 64 + k] = f2ull(b, b);
        }
        __syncthreads();

        unsigned long long a0[4], a1[4];
#pragma unroll
        for (int i = 0; i < 4; i++) { a0[i] = 0ull; a1[i] = 0ull; }
        const float* wp = Ws + c4;
        const unsigned long long* v0 = vsd + (warp * 4) * 130;
        for (int k2 = 0; k2 < 64; k2++) {
            ulonglong2 wa = *(const ulonglong2*)(wp + (2 * k2) * 128);
            ulonglong2 wb = *(const ulonglong2*)(wp + (2 * k2 + 1) * 128);
#pragma unroll
            for (int i = 0; i < 4; i++) {
                ulonglong2 vv = *(const ulonglong2*)(v0 + i * 130 + 2 * k2);
                ffma2(a0[i], wa.x, vv.x); ffma2(a1[i], wa.y, vv.x);
                ffma2(a0[i], wb.x, vv.y); ffma2(a1[i], wb.y, vv.y);
            }
        }
        {   // k = 128 (edge-attr row)
            ulonglong2 wt = *(const ulonglong2*)(wp + 128 * 128);
#pragma unroll
            for (int i = 0; i < 4; i++) {
                unsigned long long vt = v0[i * 130 + 128];
                ffma2(a0[i], wt.x, vt); ffma2(a1[i], wt.y, vt);
            }
        }
#pragma unroll
        for (int i = 0; i < 4; i++) {
            int ln = warp * 4 + i;
            int gn = base + ln;
            if (gn < N_NODES) {
                float d = dg[ln];
                float2 lo = ull2f2(a0[i]), hi = ull2f2(a1[i]);
                float4 r;
                r.x = fmaxf(fmaf(d, bs[c4 + 0], lo.x), 0.f);
                r.y = fmaxf(fmaf(d, bs[c4 + 1], lo.y), 0.f);
                r.z = fmaxf(fmaf(d, bs[c4 + 2], hi.x), 0.f);
                r.w = fmaxf(fmaf(d, bs[c4 + 3], hi.y), 0.f);
                *(float4*)&g_h[gn * 128 + c4] = r;
            }
        }
    }
}

// ==================== z = h @ Wj2  (Wj2 = W2 rows 128..255) ====================
#define DZ_N 32
__global__ __launch_bounds__(256) void zmm_kernel(const float* __restrict__ W2) {
    extern __shared__ float sm[];
    float* Ws = sm;                      // 128*64 = 8192
    unsigned long long* vsd = (unsigned long long*)(Ws + 8192); // 32 x 130 ull
    int tid = threadIdx.x;
    int warp = tid >> 5, lane = tid & 31;
    int j2 = lane * 2;
    for (int i = tid; i < 8192; i += 256) Ws[i] = W2[128 * 64 + i];

    int iters = (N_NODES + DZ_N - 1) / DZ_N;
    for (int it = blockIdx.x; it < iters; it += gridDim.x) {
        int base = it * DZ_N;
        __syncthreads();
        for (int idx = tid; idx < DZ_N * 128; idx += 256) {
            int n = idx >> 7, k = idx & 127;
            int gn = base + n;
            float hv = (gn < N_NODES) ? g_h[gn * 128 + k] : 0.f;
            vsd[n * 130 + k] = f2ull(hv, hv);
        }
        __syncthreads();

        unsigned long long acc[4];
#pragma unroll
        for (int i = 0; i < 4; i++) acc[i] = 0ull;
        const float* wp = Ws + j2;
        const unsigned long long* v0 = vsd + (warp * 4) * 130;
        for (int k4 = 0; k4 < 32; k4++) {
            int k = k4 * 4;
            unsigned long long w0 = *(const unsigned long long*)(wp + (k + 0) * 64);
            unsigned long long w1 = *(const unsigned long long*)(wp + (k + 1) * 64);
            unsigned long long w2 = *(const unsigned long long*)(wp + (k + 2) * 64);
            unsigned long long w3 = *(const unsigned long long*)(wp + (k + 3) * 64);
#pragma unroll
            for (int i = 0; i < 4; i++) {
                ulonglong2 va = *(const ulonglong2*)(v0 + i * 130 + k);
                ulonglong2 vb = *(const ulonglong2*)(v0 + i * 130 + k + 2);
                ffma2(acc[i], w0, va.x);
                ffma2(acc[i], w1, va.y);
                ffma2(acc[i], w2, vb.x);
                ffma2(acc[i], w3, vb.y);
            }
        }
#pragma unroll
        for (int i = 0; i < 4; i++) {
            int gn = base + warp * 4 + i;
            if (gn < N_NODES) {
                float2 r = ull2f2(acc[i]);
                *(float2*)&g_z[gn * 64 + j2] = r;
            }
        }
    }
}

// ==================== dense layer 2' (K=128) + fused relu & log_softmax =======
// out = log_softmax( relu( degp1*(h@Wi2 + b2) + Szz + se*We2 ) )
#define D2_N 32
__global__ __launch_bounds__(256) void dense2_kernel(
    const float* __restrict__ W2, const float* __restrict__ b2,
    float* __restrict__ out) {
    extern __shared__ float sm[];
    float* Ws = sm;                      // 128*64 = 8192 (Wi2 rows 0..127)
    float* bs = Ws + 8192;               // 64
    float* we = bs + 64;                 // 64 (We2 = W2 row 256)
    float* dg = we + 64;                 // 32
    float* sep = dg + 32;                // 32
    unsigned long long* vsd = (unsigned long long*)(sep + 32); // 32 x 130 ull
    int tid = threadIdx.x;
    int warp = tid >> 5, lane = tid & 31;
    int j2 = lane * 2;
    for (int i = tid; i < 8192; i += 256) Ws[i] = W2[i];
    if (tid < 64)  bs[tid] = b2[tid];
    else if (tid < 128) we[tid - 64] = W2[256 * 64 + (tid - 64)];

    int iters = (N_NODES + D2_N - 1) / D2_N;
    for (int it = blockIdx.x; it < iters; it += gridDim.x) {
        int base = it * D2_N;
        __syncthreads();
        if (tid < D2_N) {
            int gn = base + tid;
            bool ok = gn < N_NODES;
            dg[tid]  = ok ? g_deg[gn] + 1.0f : 1.0f;
            sep[tid] = ok ? g_se[gn] : 0.0f;
        }
        __syncthreads();
        for (int idx = tid; idx < D2_N * 128; idx += 256) {
            int n = idx >> 7, k = idx & 127;
            int gn = base + n;
            float hv = (gn < N_NODES) ? g_h[gn * 128 + k] : 0.f;
            float a = dg[n] * hv;
            vsd[n * 130 + k] = f2ull(a, a);
        }
        __syncthreads();

        unsigned long long acc[4];
#pragma unroll
        for (int i = 0; i < 4; i++) acc[i] = 0ull;
        const float* wp = Ws + j2;
        const unsigned long long* v0 = vsd + (warp * 4) * 130;
        for (int k4 = 0; k4 < 32; k4++) {
            int k = k4 * 4;
            unsigned long long w0 = *(const unsigned long long*)(wp + (k + 0) * 64);
            unsigned long long w1 = *(const unsigned long long*)(wp + (k + 1) * 64);
            unsigned long long w2 = *(const unsigned long long*)(wp + (k + 2) * 64);
            unsigned long long w3 = *(const unsigned long long*)(wp + (k + 3) * 64);
#pragma unroll
            for (int i = 0; i < 4; i++) {
                ulonglong2 va = *(const ulonglong2*)(v0 + i * 130 + k);
                ulonglong2 vb = *(const ulonglong2*)(v0 + i * 130 + k + 2);
                ffma2(acc[i], w0, va.x);
                ffma2(acc[i], w1, va.y);
                ffma2(acc[i], w2, vb.x);
                ffma2(acc[i], w3, vb.y);
            }
        }

        float bx = bs[j2], by = bs[j2 + 1];
        float wex = we[j2], wey = we[j2 + 1];
#pragma unroll
        for (int i = 0; i < 4; i++) {
            int ln = warp * 4 + i;
            int gn = base + ln;
            float d = dg[ln], se = sep[ln];
            float2 a = ull2f2(acc[i]);
            float2 szz = make_float2(0.f, 0.f);
            if (gn < N_NODES) szz = *(const float2*)&g_Szz[gn * 64 + j2];
            float rx = fmaxf(fmaf(d, bx, a.x) + szz.x + se * wex, 0.f);
            float ry = fmaxf(fmaf(d, by, a.y) + szz.y + se * wey, 0.f);
            float m = fmaxf(rx, ry);
#pragma unroll
            for (int o = 16; o; o >>= 1) m = fmaxf(m, __shfl_xor_sync(0xffffffffu, m, o));
            float s = __expf(rx - m) + __expf(ry - m);
#pragma unroll
            for (int o = 16; o; o >>= 1) s += __shfl_xor_sync(0xffffffffu, s, o);
            float ls = __logf(s) + m;
            if (gn < N_NODES) {
                float2 r = make_float2(rx - ls, ry - ls);
                *(float2*)&out[gn * 64 + j2] = r;
            }
        }
    }
}

// ---------------- launch ------------------------------------------------------
extern "C" void kernel_launch(void* const* d_in, const int* in_sizes, int n_in,
                              void* d_out, int out_size) {
    const float* x  = (const float*)d_in[0];
    const void*  ei = d_in[1];
    const float* ea = (const float*)d_in[2];
    const float* W1 = (const float*)d_in[3];
    const float* b1 = (const float*)d_in[4];
    const float* W2 = (const float*)d_in[5];
    const float* b2 = (const float*)d_in[6];
    float* out = (float*)d_out;

    int smem1 = (16512 + 128 + 32 + 32) * 4 + 32 * 130 * 8;       // 100,096 B
    int smemz = 8192 * 4 + 32 * 130 * 8;                          //  66,048 B
    int smem2 = (8192 + 64 + 64 + 32 + 32) * 4 + 32 * 130 * 8;    //  66,816 B
    cudaFuncSetAttribute(dense1_kernel, cudaFuncAttributeMaxDynamicSharedMemorySize, smem1);
    cudaFuncSetAttribute(zmm_kernel,    cudaFuncAttributeMaxDynamicSharedMemorySize, smemz);
    cudaFuncSetAttribute(dense2_kernel, cudaFuncAttributeMaxDynamicSharedMemorySize, smem2);

    zero_kernel<<<256, 256>>>((const int*)ei);
    hist_kernel<<<(N_EDGES + 255) / 256, 256>>>(ei, ea);
    scan1_kernel<<<SCAN_BLOCKS, 256>>>();
    scan2_kernel<<<1, 256>>>();
    scan3_kernel<<<SCAN_BLOCKS, 256>>>();
    fill_kernel<<<(N_EDGES + 255) / 256, 256>>>(ei);
    pull1_kernel<<<(N_NODES * 16 + 255) / 256, 256>>>(x);
    dense1_kernel<<<296, 256, smem1>>>(x, W1, b1);
    zmm_kernel<<<444, 256, smemz>>>(W2);
    pull2z_kernel<<<(N_NODES * 16 + 255) / 256, 256>>>();
    dense2_kernel<<<444, 256, smem2>>>(W2, b2, out);
}

// round 10
// speedup vs baseline: 1.5836x; 1.5836x over previous
#include <cuda_runtime.h>

#define N_NODES 50000
#define N_EDGES 800000
#define IN_C 64
#define HID_C 128
#define OUT_C 64
#define SCAN_BLOCKS 196   // 196*256 = 50176 >= N_NODES

typedef unsigned long long ull;

// ---------------- scratch (static device globals; no allocation) ----------------
__device__ float g_Sx[N_NODES * IN_C];    // sum_{src->d} x[src]
__device__ float g_S2[N_NODES * HID_C];   // sum_{src->d} h[src]
__device__ float g_h [N_NODES * HID_C];   // hidden activations
__device__ float g_deg[N_NODES];          // in-degree
__device__ float g_se [N_NODES];          // sum of edge_attr per dst
__device__ int   g_cnt[N_NODES];          // histogram counts
__device__ int   g_rp [N_NODES];          // CSR row pointer
__device__ int   g_cur[N_NODES];          // fill cursors
__device__ int   g_bs [256];              // block sums for 2-level scan
__device__ int   g_srcs[N_EDGES];         // CSR column (src) indices
__device__ int   g_any;                   // != 0 -> edge_index is int32

// ---------------- f32x2 packed helpers ----------------
__device__ __forceinline__ void ffma2(ull& acc, ull a, ull b) {
    asm("fma.rn.f32x2 %0, %1, %2, %0;" : "+l"(acc) : "l"(a), "l"(b));
}
__device__ __forceinline__ ull f2ull(float a, float b) {
    ull u;
    asm("mov.b64 %0, {%1, %2};" : "=l"(u) : "f"(a), "f"(b));
    return u;
}
__device__ __forceinline__ float2 ull2f2(ull u) {
    float2 f;
    asm("mov.b64 {%0, %1}, %2;" : "=f"(f.x), "=f"(f.y) : "l"(u));
    return f;
}
__device__ __forceinline__ float pairsum(ull u) {
    float2 f = ull2f2(u);
    return f.x + f.y;
}

// ---------------- zero small scratch + dtype detect ----------------
__global__ void zero_kernel(const int* __restrict__ ei32) {
    int i = blockIdx.x * blockDim.x + threadIdx.x;
    int stride = gridDim.x * blockDim.x;
    for (int k = i; k < N_NODES; k += stride) { g_cnt[k] = 0; g_se[k] = 0.f; }
    if (blockIdx.x == 0) {
        if (threadIdx.x == 0) g_any = 0;
        __syncthreads();
        int v = 0;
        for (int k = threadIdx.x; k < 1024; k += blockDim.x) v |= ei32[2 * k + 1];
        if (v) atomicOr(&g_any, 1);
    }
}

__device__ __forceinline__ void load_edge(const void* ei, int e, bool is64,
                                          int& src, int& dst) {
    if (is64) {
        const long long* p = (const long long*)ei;
        src = (int)__ldg(p + e); dst = (int)__ldg(p + N_EDGES + e);
    } else {
        const int* p = (const int*)ei;
        src = __ldg(p + e); dst = __ldg(p + N_EDGES + e);
    }
}

// ---------------- CSR build ----------------
__global__ __launch_bounds__(256) void hist_kernel(const void* __restrict__ ei,
                                                   const float* __restrict__ ea) {
    int e = blockIdx.x * blockDim.x + threadIdx.x;
    if (e >= N_EDGES) return;
    bool is64 = (g_any == 0);
    int src, dst;
    load_edge(ei, e, is64, src, dst);
    atomicAdd(&g_cnt[dst], 1);
    atomicAdd(&g_se[dst], __ldg(ea + e));
}

__global__ __launch_bounds__(256) void scan1_kernel() {
    __shared__ int s[256];
    int t = threadIdx.x;
    int i = blockIdx.x * 256 + t;
    int c = (i < N_NODES) ? g_cnt[i] : 0;
    s[t] = c;
    __syncthreads();
    for (int o = 1; o < 256; o <<= 1) {
        int v = (t >= o) ? s[t - o] : 0;
        __syncthreads();
        s[t] += v;
        __syncthreads();
    }
    if (i < N_NODES) g_rp[i] = s[t] - c;
    if (t == 255) g_bs[blockIdx.x] = s[255];
}

__global__ __launch_bounds__(256) void scan2_kernel() {
    __shared__ int s[256];
    int t = threadIdx.x;
    int c = (t < SCAN_BLOCKS) ? g_bs[t] : 0;
    s[t] = c;
    __syncthreads();
    for (int o = 1; o < 256; o <<= 1) {
        int v = (t >= o) ? s[t - o] : 0;
        __syncthreads();
        s[t] += v;
        __syncthreads();
    }
    if (t < SCAN_BLOCKS) g_bs[t] = s[t] - c;
}

__global__ __launch_bounds__(256) void scan3_kernel() {
    int i = blockIdx.x * 256 + threadIdx.x;
    if (i >= N_NODES) return;
    int rp = g_rp[i] + g_bs[i >> 8];
    g_rp[i] = rp;
    g_cur[i] = rp;
    g_deg[i] = (float)g_cnt[i];
}

__global__ __launch_bounds__(256) void fill_kernel(const void* __restrict__ ei) {
    int e = blockIdx.x * blockDim.x + threadIdx.x;
    if (e >= N_EDGES) return;
    bool is64 = (g_any == 0);
    int src, dst;
    load_edge(ei, e, is64, src, dst);
    int p = atomicAdd(&g_cur[dst], 1);
    g_srcs[p] = src;
}

// ---------------- pull layer 1: 16 threads per dst, 64 ch as float4 ----------
__global__ __launch_bounds__(256) void pull1_kernel(const float* __restrict__ x) {
    int tid = blockIdx.x * blockDim.x + threadIdx.x;
    int d = tid >> 4, c = tid & 15;
    if (d >= N_NODES) return;
    int beg = g_rp[d];
    int end = beg + g_cnt[d];
    float4 acc = make_float4(0.f, 0.f, 0.f, 0.f);
#pragma unroll 4
    for (int j = beg; j < end; j++) {
        int s = __ldg(&g_srcs[j]);
        float4 v = __ldg((const float4*)x + s * (IN_C / 4) + c);
        acc.x += v.x; acc.y += v.y; acc.z += v.z; acc.w += v.w;
    }
    ((float4*)g_Sx)[d * (IN_C / 4) + c] = acc;
}

// ---------------- pull layer 2: warp per dst, 128 ch as float4 ---------------
__global__ __launch_bounds__(256) void pull2_kernel() {
    int tid = blockIdx.x * blockDim.x + threadIdx.x;
    int d = tid >> 5, c = tid & 31;
    if (d >= N_NODES) return;
    int beg = g_rp[d];
    int end = beg + g_cnt[d];
    float4 acc = make_float4(0.f, 0.f, 0.f, 0.f);
#pragma unroll 4
    for (int j = beg; j < end; j++) {
        int s = __ldg(&g_srcs[j]);
        float4 v = __ldg((const float4*)g_h + s * (HID_C / 4) + c);
        acc.x += v.x; acc.y += v.y; acc.z += v.z; acc.w += v.w;
    }
    ((float4*)g_S2)[d * (HID_C / 4) + c] = acc;
}

// ==================== dense layer 1 (k-paired FFMA2) ====================
// h = relu( v @ W1 + degp1*b1 ), v = [degp1*x (64), Sx+x (64), se (1)]
// W pre-paired over k: Wp[k2*128+j] = (W1[2k2][j], W1[2k2+1][j]).
// acc = (sum over even k, sum over odd k); final = lo+hi.
#define D1_N 32
__global__ __launch_bounds__(256) void dense1_kernel(
    const float* __restrict__ x, const float* __restrict__ W1,
    const float* __restrict__ b1) {
    extern __shared__ float sm[];
    ull*   Wp = (ull*)sm;                 // 64 pairs x 128 cols = 8192 ull (64KB)
    float* vp = (float*)(Wp + 8192);      // 32 nodes x 128 floats (16KB)
    float* bs = vp + 32 * 128;            // 128
    float* we = bs + 128;                 // 128 (W1 row 128)
    float* dg = we + 128;                 // 32
    float* sep = dg + 32;                 // 32
    int tid = threadIdx.x;
    int warp = tid >> 5, lane = tid & 31;
    int c4 = lane * 4;
    for (int i = tid; i < 8192; i += 256) {
        int k2 = i >> 7, j = i & 127;
        Wp[i] = f2ull(W1[(2 * k2) * 128 + j], W1[(2 * k2 + 1) * 128 + j]);
    }
    if (tid < 128) { bs[tid] = b1[tid]; we[tid] = W1[128 * 128 + tid]; }

    int iters = (N_NODES + D1_N - 1) / D1_N;
    for (int it = blockIdx.x; it < iters; it += gridDim.x) {
        int base = it * D1_N;
        __syncthreads();                  // vp/dg reuse (and W load on first pass)
        if (tid < D1_N) {
            int gn = base + tid;
            bool ok = gn < N_NODES;
            dg[tid]  = ok ? g_deg[gn] + 1.0f : 1.0f;
            sep[tid] = ok ? g_se[gn] : 0.0f;
        }
        __syncthreads();
        for (int idx = tid; idx < D1_N * 64; idx += 256) {
            int n = idx >> 6, k = idx & 63;
            int gn = base + n;
            float xv = 0.f, sv = 0.f;
            if (gn < N_NODES) { xv = x[gn * 64 + k]; sv = g_Sx[gn * 64 + k]; }
            vp[n * 128 + k]      = dg[n] * xv;
            vp[n * 128 + 64 + k] = sv + xv;
        }
        __syncthreads();

        ull acc[4][4];
#pragma unroll
        for (int i = 0; i < 4; i++)
#pragma unroll
            for (int c = 0; c < 4; c++) acc[i][c] = 0ull;
        const float* v0 = vp + (warp * 4) * 128;
#pragma unroll 2
        for (int k2 = 0; k2 < 64; k2++) {
            ulonglong2 wA = *(const ulonglong2*)&Wp[k2 * 128 + c4];
            ulonglong2 wB = *(const ulonglong2*)&Wp[k2 * 128 + c4 + 2];
#pragma unroll
            for (int i = 0; i < 4; i++) {
                ull vv = *(const ull*)(v0 + i * 128 + 2 * k2);   // LDS.64 broadcast
                ffma2(acc[i][0], wA.x, vv);
                ffma2(acc[i][1], wA.y, vv);
                ffma2(acc[i][2], wB.x, vv);
                ffma2(acc[i][3], wB.y, vv);
            }
        }
#pragma unroll
        for (int i = 0; i < 4; i++) {
            int ln = warp * 4 + i;
            int gn = base + ln;
            if (gn < N_NODES) {
                float d = dg[ln], se = sep[ln];
                float4 r;
                r.x = fmaxf(pairsum(acc[i][0]) + fmaf(d, bs[c4 + 0], se * we[c4 + 0]), 0.f);
                r.y = fmaxf(pairsum(acc[i][1]) + fmaf(d, bs[c4 + 1], se * we[c4 + 1]), 0.f);
                r.z = fmaxf(pairsum(acc[i][2]) + fmaf(d, bs[c4 + 2], se * we[c4 + 2]), 0.f);
                r.w = fmaxf(pairsum(acc[i][3]) + fmaf(d, bs[c4 + 3], se * we[c4 + 3]), 0.f);
                *(float4*)&g_h[gn * 128 + c4] = r;
            }
        }
    }
}

// ==================== dense layer 2 (k-paired) + fused relu & log_softmax ====
// out = log_softmax( relu( v @ W2 + degp1*b2 ) ), v = [degp1*h (128), S2+h (128), se]
// Wp2[k2*64+j] = (W2[2k2][j], W2[2k2+1][j]), k2 = 0..127; row 256 = We separate.
#define D2_N 32
__global__ __launch_bounds__(256) void dense2_kernel(
    const float* __restrict__ W2, const float* __restrict__ b2,
    float* __restrict__ out) {
    extern __shared__ float sm[];
    ull*   Wp = (ull*)sm;                 // 128 pairs x 64 cols = 8192 ull (64KB)
    float* vp = (float*)(Wp + 8192);      // 32 nodes x 256 floats (32KB)
    float* bs = vp + 32 * 256;            // 64
    float* we = bs + 64;                  // 64 (W2 row 256)
    float* dg = we + 64;                  // 32
    float* sep = dg + 32;                 // 32
    int tid = threadIdx.x;
    int warp = tid >> 5, lane = tid & 31;
    int j2 = lane * 2;
    for (int i = tid; i < 8192; i += 256) {
        int k2 = i >> 6, j = i & 63;
        Wp[i] = f2ull(W2[(2 * k2) * 64 + j], W2[(2 * k2 + 1) * 64 + j]);
    }
    if (tid < 64) { bs[tid] = b2[tid]; we[tid] = W2[256 * 64 + tid]; }

    int iters = (N_NODES + D2_N - 1) / D2_N;
    for (int it = blockIdx.x; it < iters; it += gridDim.x) {
        int base = it * D2_N;
        __syncthreads();
        if (tid < D2_N) {
            int gn = base + tid;
            bool ok = gn < N_NODES;
            dg[tid]  = ok ? g_deg[gn] + 1.0f : 1.0f;
            sep[tid] = ok ? g_se[gn] : 0.0f;
        }
        __syncthreads();
        for (int idx = tid; idx < D2_N * 128; idx += 256) {
            int n = idx >> 7, k = idx & 127;
            int gn = base + n;
            float hv = 0.f, sv = 0.f;
            if (gn < N_NODES) { hv = g_h[gn * 128 + k]; sv = g_S2[gn * 128 + k]; }
            vp[n * 256 + k]       = dg[n] * hv;
            vp[n * 256 + 128 + k] = sv + hv;
        }
        __syncthreads();

        ull acc[4][2];
#pragma unroll
        for (int i = 0; i < 4; i++) { acc[i][0] = 0ull; acc[i][1] = 0ull; }
        const float* v0 = vp + (warp * 4) * 256;
#pragma unroll 4
        for (int k2 = 0; k2 < 128; k2++) {
            ulonglong2 w = *(const ulonglong2*)&Wp[k2 * 64 + j2];
#pragma unroll
            for (int i = 0; i < 4; i++) {
                ull vv = *(const ull*)(v0 + i * 256 + 2 * k2);   // LDS.64 broadcast
                ffma2(acc[i][0], w.x, vv);
                ffma2(acc[i][1], w.y, vv);
            }
        }

        float bx = bs[j2], by = bs[j2 + 1];
        float wex = we[j2], wey = we[j2 + 1];
#pragma unroll
        for (int i = 0; i < 4; i++) {
            int ln = warp * 4 + i;
            int gn = base + ln;
            float d = dg[ln], se = sep[ln];
            float rx = fmaxf(pairsum(acc[i][0]) + fmaf(d, bx, se * wex), 0.f);
            float ry = fmaxf(pairsum(acc[i][1]) + fmaf(d, by, se * wey), 0.f);
            float m = fmaxf(rx, ry);
#pragma unroll
            for (int o = 16; o; o >>= 1) m = fmaxf(m, __shfl_xor_sync(0xffffffffu, m, o));
            float s = __expf(rx - m) + __expf(ry - m);
#pragma unroll
            for (int o = 16; o; o >>= 1) s += __shfl_xor_sync(0xffffffffu, s, o);
            float ls = __logf(s) + m;
            if (gn < N_NODES) {
                float2 r = make_float2(rx - ls, ry - ls);
                *(float2*)&out[gn * 64 + j2] = r;
            }
        }
    }
}

// ---------------- launch ------------------------------------------------------
extern "C" void kernel_launch(void* const* d_in, const int* in_sizes, int n_in,
                              void* d_out, int out_size) {
    const float* x  = (const float*)d_in[0];
    const void*  ei = d_in[1];
    const float* ea = (const float*)d_in[2];
    const float* W1 = (const float*)d_in[3];
    const float* b1 = (const float*)d_in[4];
    const float* W2 = (const float*)d_in[5];
    const float* b2 = (const float*)d_in[6];
    float* out = (float*)d_out;

    int smem1 = 8192 * 8 + 32 * 128 * 4 + (128 + 128 + 32 + 32) * 4;  // 83,200 B
    int smem2 = 8192 * 8 + 32 * 256 * 4 + (64 + 64 + 32 + 32) * 4;    // 99,072 B
    cudaFuncSetAttribute(dense1_kernel, cudaFuncAttributeMaxDynamicSharedMemorySize, smem1);
    cudaFuncSetAttribute(dense2_kernel, cudaFuncAttributeMaxDynamicSharedMemorySize, smem2);

    zero_kernel<<<256, 256>>>((const int*)ei);
    hist_kernel<<<(N_EDGES + 255) / 256, 256>>>(ei, ea);
    scan1_kernel<<<SCAN_BLOCKS, 256>>>();
    scan2_kernel<<<1, 256>>>();
    scan3_kernel<<<SCAN_BLOCKS, 256>>>();
    fill_kernel<<<(N_EDGES + 255) / 256, 256>>>(ei);
    pull1_kernel<<<(N_NODES * 16 + 255) / 256, 256>>>(x);
    dense1_kernel<<<296, 256, smem1>>>(x, W1, b1);
    pull2_kernel<<<(N_NODES * 32 + 255) / 256, 256>>>();
    dense2_kernel<<<296, 256, smem2>>>(W2, b2, out);
}

// round 13
// speedup vs baseline: 1.6972x; 1.0717x over previous
#include <cuda_runtime.h>

#define N_NODES 50000
#define N_EDGES 800000
#define IN_C 64
#define HID_C 128
#define OUT_C 64
#define SCAN_BLOCKS 196   // 196*256 = 50176 >= N_NODES

typedef unsigned long long ull;

// ---------------- scratch (static device globals; no allocation) ----------------
__device__ float g_Sx[N_NODES * IN_C];    // sum_{src->d} x[src]
__device__ float g_S2[N_NODES * HID_C];   // sum_{src->d} h[src]
__device__ float g_h [N_NODES * HID_C];   // hidden activations
__device__ float g_deg[N_NODES];          // in-degree
__device__ float g_se [N_NODES];          // sum of edge_attr per dst
__device__ int   g_cnt[N_NODES];          // histogram counts
__device__ int   g_rp [N_NODES];          // CSR row pointer
__device__ int   g_cur[N_NODES];          // fill cursors
__device__ int   g_bs [256];              // block sums for 2-level scan
__device__ int   g_srcs[N_EDGES];         // CSR column (src) indices
__device__ int   g_any;                   // != 0 -> edge_index is int32

// ---------------- f32x2 packed helpers ----------------
__device__ __forceinline__ void ffma2(ull& acc, ull a, ull b) {
    asm("fma.rn.f32x2 %0, %1, %2, %0;" : "+l"(acc) : "l"(a), "l"(b));
}
__device__ __forceinline__ ull f2ull(float a, float b) {
    ull u;
    asm("mov.b64 %0, {%1, %2};" : "=l"(u) : "f"(a), "f"(b));
    return u;
}
__device__ __forceinline__ float2 ull2f2(ull u) {
    float2 f;
    asm("mov.b64 {%0, %1}, %2;" : "=f"(f.x), "=f"(f.y) : "l"(u));
    return f;
}
__device__ __forceinline__ float pairsum(ull u) {
    float2 f = ull2f2(u);
    return f.x + f.y;
}

// ---------------- zero small scratch + dtype detect ----------------
__global__ void zero_kernel(const int* __restrict__ ei32) {
    int i = blockIdx.x * blockDim.x + threadIdx.x;
    int stride = gridDim.x * blockDim.x;
    for (int k = i; k < N_NODES; k += stride) { g_cnt[k] = 0; g_se[k] = 0.f; }
    if (blockIdx.x == 0) {
        if (threadIdx.x == 0) g_any = 0;
        __syncthreads();
        int v = 0;
        for (int k = threadIdx.x; k < 1024; k += blockDim.x) v |= ei32[2 * k + 1];
        if (v) atomicOr(&g_any, 1);
    }
}

__device__ __forceinline__ void load_edge(const void* ei, int e, bool is64,
                                          int& src, int& dst) {
    if (is64) {
        const long long* p = (const long long*)ei;
        src = (int)__ldg(p + e); dst = (int)__ldg(p + N_EDGES + e);
    } else {
        const int* p = (const int*)ei;
        src = __ldg(p + e); dst = __ldg(p + N_EDGES + e);
    }
}

// ---------------- CSR build ----------------
__global__ __launch_bounds__(256) void hist_kernel(const void* __restrict__ ei,
                                                   const float* __restrict__ ea) {
    int e = blockIdx.x * blockDim.x + threadIdx.x;
    if (e >= N_EDGES) return;
    bool is64 = (g_any == 0);
    int src, dst;
    load_edge(ei, e, is64, src, dst);
    atomicAdd(&g_cnt[dst], 1);
    atomicAdd(&g_se[dst], __ldg(ea + e));
}

__global__ __launch_bounds__(256) void scan1_kernel() {
    __shared__ int s[256];
    int t = threadIdx.x;
    int i = blockIdx.x * 256 + t;
    int c = (i < N_NODES) ? g_cnt[i] : 0;
    s[t] = c;
    __syncthreads();
    for (int o = 1; o < 256; o <<= 1) {
        int v = (t >= o) ? s[t - o] : 0;
        __syncthreads();
        s[t] += v;
        __syncthreads();
    }
    if (i < N_NODES) g_rp[i] = s[t] - c;
    if (t == 255) g_bs[blockIdx.x] = s[255];
}

__global__ __launch_bounds__(256) void scan2_kernel() {
    __shared__ int s[256];
    int t = threadIdx.x;
    int c = (t < SCAN_BLOCKS) ? g_bs[t] : 0;
    s[t] = c;
    __syncthreads();
    for (int o = 1; o < 256; o <<= 1) {
        int v = (t >= o) ? s[t - o] : 0;
        __syncthreads();
        s[t] += v;
        __syncthreads();
    }
    if (t < SCAN_BLOCKS) g_bs[t] = s[t] - c;
}

__global__ __launch_bounds__(256) void scan3_kernel() {
    int i = blockIdx.x * 256 + threadIdx.x;
    if (i >= N_NODES) return;
    int rp = g_rp[i] + g_bs[i >> 8];
    g_rp[i] = rp;
    g_cur[i] = rp;
    g_deg[i] = (float)g_cnt[i];
}

__global__ __launch_bounds__(256) void fill_kernel(const void* __restrict__ ei) {
    int e = blockIdx.x * blockDim.x + threadIdx.x;
    if (e >= N_EDGES) return;
    bool is64 = (g_any == 0);
    int src, dst;
    load_edge(ei, e, is64, src, dst);
    int p = atomicAdd(&g_cur[dst], 1);
    g_srcs[p] = src;
}

// ---------------- pull layer 1: 16 threads per dst, 64 ch as float4 ----------
__global__ __launch_bounds__(256) void pull1_kernel(const float* __restrict__ x) {
    int tid = blockIdx.x * blockDim.x + threadIdx.x;
    int d = tid >> 4, c = tid & 15;
    if (d >= N_NODES) return;
    int beg = g_rp[d];
    int end = beg + g_cnt[d];
    float4 acc = make_float4(0.f, 0.f, 0.f, 0.f);
#pragma unroll 4
    for (int j = beg; j < end; j++) {
        int s = __ldg(&g_srcs[j]);
        float4 v = __ldg((const float4*)x + s * (IN_C / 4) + c);
        acc.x += v.x; acc.y += v.y; acc.z += v.z; acc.w += v.w;
    }
    ((float4*)g_Sx)[d * (IN_C / 4) + c] = acc;
}

// ---------------- pull layer 2: warp per dst, 128 ch as float4 ---------------
__global__ __launch_bounds__(256) void pull2_kernel() {
    int tid = blockIdx.x * blockDim.x + threadIdx.x;
    int d = tid >> 5, c = tid & 31;
    if (d >= N_NODES) return;
    int beg = g_rp[d];
    int end = beg + g_cnt[d];
    float4 acc = make_float4(0.f, 0.f, 0.f, 0.f);
#pragma unroll 4
    for (int j = beg; j < end; j++) {
        int s = __ldg(&g_srcs[j]);
        float4 v = __ldg((const float4*)g_h + s * (HID_C / 4) + c);
        acc.x += v.x; acc.y += v.y; acc.z += v.z; acc.w += v.w;
    }
    ((float4*)g_S2)[d * (HID_C / 4) + c] = acc;
}

// ==================== dense layer 1 (8 nodes x 2 cols per warp) ====================
// h = relu( v @ W1 + degp1*b1 ), v = [degp1*x (64), Sx+x (64), se (1)]
// Wp[p*128+j] = (W1[2p][j], W1[2p+1][j]); loop p by 2, v loaded as bcast LDS.128
// covering 4 k's. acc = (even-k sum, odd-k sum); final = lo+hi.
#define D1_N 32
__global__ __launch_bounds__(256) void dense1_kernel(
    const float* __restrict__ x, const float* __restrict__ W1,
    const float* __restrict__ b1) {
    extern __shared__ float sm[];
    ull*   Wp = (ull*)sm;                 // 64 pair-rows x 128 cols (64KB)
    float* vp = (float*)(Wp + 8192);      // 32 nodes x 128 floats (16KB)
    float* bs = vp + 32 * 128;            // 128
    float* we = bs + 128;                 // 128 (W1 row 128)
    float* dg = we + 128;                 // 32
    float* sep = dg + 32;                 // 32
    int tid = threadIdx.x;
    int warp = tid >> 5, lane = tid & 31;
    int ng = warp >> 1;                   // node group (0..3) -> 8 nodes
    int j2 = (warp & 1) * 64 + lane * 2;  // 2 output cols
    for (int i = tid; i < 8192; i += 256) {
        int p = i >> 7, j = i & 127;
        Wp[i] = f2ull(W1[(2 * p) * 128 + j], W1[(2 * p + 1) * 128 + j]);
    }
    if (tid < 128) { bs[tid] = b1[tid]; we[tid] = W1[128 * 128 + tid]; }

    int iters = (N_NODES + D1_N - 1) / D1_N;
    for (int it = blockIdx.x; it < iters; it += gridDim.x) {
        int base = it * D1_N;
        __syncthreads();                  // vp/dg reuse (and W load on first pass)
        if (tid < D1_N) {
            int gn = base + tid;
            bool ok = gn < N_NODES;
            dg[tid]  = ok ? g_deg[gn] + 1.0f : 1.0f;
            sep[tid] = ok ? g_se[gn] : 0.0f;
        }
        __syncthreads();
        for (int idx = tid; idx < D1_N * 64; idx += 256) {
            int n = idx >> 6, k = idx & 63;
            int gn = base + n;
            float xv = 0.f, sv = 0.f;
            if (gn < N_NODES) { xv = x[gn * 64 + k]; sv = g_Sx[gn * 64 + k]; }
            vp[n * 128 + k]      = dg[n] * xv;
            vp[n * 128 + 64 + k] = sv + xv;
        }
        __syncthreads();

        ull acc[8][2];
#pragma unroll
        for (int n = 0; n < 8; n++) { acc[n][0] = 0ull; acc[n][1] = 0ull; }
        const float* v0 = vp + (ng * 8) * 128;
#pragma unroll 2
        for (int p = 0; p < 64; p += 2) {
            ulonglong2 w0 = *(const ulonglong2*)&Wp[p * 128 + j2];        // k 2p,2p+1
            ulonglong2 w1 = *(const ulonglong2*)&Wp[(p + 1) * 128 + j2];  // k 2p+2,2p+3
#pragma unroll
            for (int n = 0; n < 8; n++) {
                ulonglong2 vv = *(const ulonglong2*)(v0 + n * 128 + 2 * p); // bcast 16B
                ffma2(acc[n][0], w0.x, vv.x);
                ffma2(acc[n][1], w0.y, vv.x);
                ffma2(acc[n][0], w1.x, vv.y);
                ffma2(acc[n][1], w1.y, vv.y);
            }
        }
        float b0 = bs[j2], b1v = bs[j2 + 1];
        float we0 = we[j2], we1 = we[j2 + 1];
#pragma unroll
        for (int n = 0; n < 8; n++) {
            int ln = ng * 8 + n;
            int gn = base + ln;
            if (gn < N_NODES) {
                float d = dg[ln], se = sep[ln];
                float2 r;
                r.x = fmaxf(pairsum(acc[n][0]) + fmaf(d, b0,  se * we0), 0.f);
                r.y = fmaxf(pairsum(acc[n][1]) + fmaf(d, b1v, se * we1), 0.f);
                *(float2*)&g_h[gn * 128 + j2] = r;
            }
        }
    }
}

// ==================== dense layer 2 (8 nodes x 2 cols per warp, 4 warps) =====
// out = log_softmax( relu( v @ W2 + degp1*b2 ) ), v = [degp1*h (128), S2+h (128), se]
// Wp[p*64+j] = (W2[2p][j], W2[2p+1][j]), p = 0..127; row 256 = We separate.
#define D2_N 32
__global__ __launch_bounds__(128) void dense2_kernel(
    const float* __restrict__ W2, const float* __restrict__ b2,
    float* __restrict__ out) {
    extern __shared__ float sm[];
    ull*   Wp = (ull*)sm;                 // 128 pair-rows x 64 cols (64KB)
    float* vp = (float*)(Wp + 8192);      // 32 nodes x 256 floats (32KB)
    float* bs = vp + 32 * 256;            // 64
    float* we = bs + 64;                  // 64 (W2 row 256)
    float* dg = we + 64;                  // 32
    float* sep = dg + 32;                 // 32
    int tid = threadIdx.x;
    int warp = tid >> 5, lane = tid & 31; // warp = node group (0..3)
    int j2 = lane * 2;
    for (int i = tid; i < 8192; i += 128) {
        int p = i >> 6, j = i & 63;
        Wp[i] = f2ull(W2[(2 * p) * 64 + j], W2[(2 * p + 1) * 64 + j]);
    }
    if (tid < 64) { bs[tid] = b2[tid]; we[tid] = W2[256 * 64 + tid]; }

    int iters = (N_NODES + D2_N - 1) / D2_N;
    for (int it = blockIdx.x; it < iters; it += gridDim.x) {
        int base = it * D2_N;
        __syncthreads();
        if (tid < D2_N) {
            int gn = base + tid;
            bool ok = gn < N_NODES;
            dg[tid]  = ok ? g_deg[gn] + 1.0f : 1.0f;
            sep[tid] = ok ? g_se[gn] : 0.0f;
        }
        __syncthreads();
        for (int idx = tid; idx < D2_N * 64; idx += 128) {
            int n = idx >> 6, kk = idx & 63;   // k = 2*kk
            int gn = base + n;
            float2 hv = make_float2(0.f, 0.f), sv = make_float2(0.f, 0.f);
            if (gn < N_NODES) {
                hv = *(const float2*)&g_h [gn * 128 + 2 * kk];
                sv = *(const float2*)&g_S2[gn * 128 + 2 * kk];
            }
            float d = dg[n];
            *(float2*)&vp[n * 256 + 2 * kk]       = make_float2(d * hv.x, d * hv.y);
            *(float2*)&vp[n * 256 + 128 + 2 * kk] = make_float2(sv.x + hv.x, sv.y + hv.y);
        }
        __syncthreads();

        ull acc[8][2];
#pragma unroll
        for (int n = 0; n < 8; n++) { acc[n][0] = 0ull; acc[n][1] = 0ull; }
        const float* v0 = vp + (warp * 8) * 256;
#pragma unroll 2
        for (int p = 0; p < 128; p += 2) {
            ulonglong2 w0 = *(const ulonglong2*)&Wp[p * 64 + j2];        // k 2p,2p+1
            ulonglong2 w1 = *(const ulonglong2*)&Wp[(p + 1) * 64 + j2];  // k 2p+2,2p+3
#pragma unroll
            for (int n = 0; n < 8; n++) {
                ulonglong2 vv = *(const ulonglong2*)(v0 + n * 256 + 2 * p); // bcast 16B
                ffma2(acc[n][0], w0.x, vv.x);
                ffma2(acc[n][1], w0.y, vv.x);
                ffma2(acc[n][0], w1.x, vv.y);
                ffma2(acc[n][1], w1.y, vv.y);
            }
        }

        float bx = bs[j2], by = bs[j2 + 1];
        float wex = we[j2], wey = we[j2 + 1];
#pragma unroll
        for (int n = 0; n < 8; n++) {
            int ln = warp * 8 + n;
            int gn = base + ln;
            float d = dg[ln], se = sep[ln];
            float rx = fmaxf(pairsum(acc[n][0]) + fmaf(d, bx, se * wex), 0.f);
            float ry = fmaxf(pairsum(acc[n][1]) + fmaf(d, by, se * wey), 0.f);
            float m = fmaxf(rx, ry);
#pragma unroll
            for (int o = 16; o; o >>= 1) m = fmaxf(m, __shfl_xor_sync(0xffffffffu, m, o));
            float s = __expf(rx - m) + __expf(ry - m);
#pragma unroll
            for (int o = 16; o; o >>= 1) s += __shfl_xor_sync(0xffffffffu, s, o);
            float ls = __logf(s) + m;
            if (gn < N_NODES) {
                float2 r = make_float2(rx - ls, ry - ls);
                *(float2*)&out[gn * 64 + j2] = r;
            }
        }
    }
}

// ---------------- launch ------------------------------------------------------
extern "C" void kernel_launch(void* const* d_in, const int* in_sizes, int n_in,
                              void* d_out, int out_size) {
    const float* x  = (const float*)d_in[0];
    const void*  ei = d_in[1];
    const float* ea = (const float*)d_in[2];
    const float* W1 = (const float*)d_in[3];
    const float* b1 = (const float*)d_in[4];
    const float* W2 = (const float*)d_in[5];
    const float* b2 = (const float*)d_in[6];
    float* out = (float*)d_out;

    int smem1 = 8192 * 8 + 32 * 128 * 4 + (128 + 128 + 32 + 32) * 4;  // 83,200 B
    int smem2 = 8192 * 8 + 32 * 256 * 4 + (64 + 64 + 32 + 32) * 4;    // 99,072 B
    cudaFuncSetAttribute(dense1_kernel, cudaFuncAttributeMaxDynamicSharedMemorySize, smem1);
    cudaFuncSetAttribute(dense2_kernel, cudaFuncAttributeMaxDynamicSharedMemorySize, smem2);

    zero_kernel<<<256, 256>>>((const int*)ei);
    hist_kernel<<<(N_EDGES + 255) / 256, 256>>>(ei, ea);
    scan1_kernel<<<SCAN_BLOCKS, 256>>>();
    scan2_kernel<<<1, 256>>>();
    scan3_kernel<<<SCAN_BLOCKS, 256>>>();
    fill_kernel<<<(N_EDGES + 255) / 256, 256>>>(ei);
    pull1_kernel<<<(N_NODES * 16 + 255) / 256, 256>>>(x);
    dense1_kernel<<<296, 256, smem1>>>(x, W1, b1);
    pull2_kernel<<<(N_NODES * 32 + 255) / 256, 256>>>();
    dense2_kernel<<<296, 128, smem2>>>(W2, b2, out);
}

// round 15
// speedup vs baseline: 1.8205x; 1.0727x over previous
#include <cuda_runtime.h>

#define N_NODES 50000
#define N_EDGES 800000
#define IN_C 64
#define HID_C 128
#define OUT_C 64
#define SCAN_BLOCKS 196   // 196*256 = 50176 >= N_NODES

typedef unsigned long long ull;

// ---------------- scratch (static device globals; no allocation) ----------------
__device__ float g_Sx[N_NODES * IN_C];    // sum_{src->d} x[src]
__device__ float g_h [N_NODES * HID_C];   // hidden activations
__device__ float g_z  [N_NODES * OUT_C];  // z = h @ Wj2
__device__ float g_Szz[N_NODES * OUT_C];  // z_self + sum_src z[src]
__device__ float g_deg[N_NODES];          // in-degree
__device__ float g_se [N_NODES];          // sum of edge_attr per dst
__device__ int   g_cnt[N_NODES];          // histogram counts
__device__ int   g_rp [N_NODES];          // CSR row pointer (block-arrival order)
__device__ int   g_cur[N_NODES];          // fill cursors
__device__ int   g_total;                 // global offset for fused scan
__device__ int   g_srcs[N_EDGES];         // CSR column (src) indices
__device__ int   g_any;                   // != 0 -> edge_index is int32

// ---------------- f32x2 packed helpers ----------------
__device__ __forceinline__ void ffma2(ull& acc, ull a, ull b) {
    asm("fma.rn.f32x2 %0, %1, %2, %0;" : "+l"(acc) : "l"(a), "l"(b));
}
__device__ __forceinline__ ull f2ull(float a, float b) {
    ull u;
    asm("mov.b64 %0, {%1, %2};" : "=l"(u) : "f"(a), "f"(b));
    return u;
}
__device__ __forceinline__ float2 ull2f2(ull u) {
    float2 f;
    asm("mov.b64 {%0, %1}, %2;" : "=f"(f.x), "=f"(f.y) : "l"(u));
    return f;
}
__device__ __forceinline__ float pairsum(ull u) {
    float2 f = ull2f2(u);
    return f.x + f.y;
}

// ---------------- zero small scratch + dtype detect ----------------
__global__ void zero_kernel(const int* __restrict__ ei32) {
    int i = blockIdx.x * blockDim.x + threadIdx.x;
    int stride = gridDim.x * blockDim.x;
    for (int k = i; k < N_NODES; k += stride) { g_cnt[k] = 0; g_se[k] = 0.f; }
    if (blockIdx.x == 0) {
        if (threadIdx.x == 0) { g_any = 0; g_total = 0; }
        __syncthreads();
        int v = 0;
        for (int k = threadIdx.x; k < 1024; k += blockDim.x) v |= ei32[2 * k + 1];
        if (v) atomicOr(&g_any, 1);
    }
}

__device__ __forceinline__ void load_edge(const void* ei, int e, bool is64,
                                          int& src, int& dst) {
    if (is64) {
        const long long* p = (const long long*)ei;
        src = (int)__ldg(p + e); dst = (int)__ldg(p + N_EDGES + e);
    } else {
        const int* p = (const int*)ei;
        src = __ldg(p + e); dst = __ldg(p + N_EDGES + e);
    }
}

// ---------------- CSR build ----------------
__global__ __launch_bounds__(256) void hist_kernel(const void* __restrict__ ei,
                                                   const float* __restrict__ ea) {
    int e = blockIdx.x * blockDim.x + threadIdx.x;
    if (e >= N_EDGES) return;
    bool is64 = (g_any == 0);
    int src, dst;
    load_edge(ei, e, is64, src, dst);
    atomicAdd(&g_cnt[dst], 1);
    atomicAdd(&g_se[dst], __ldg(ea + e));
}

// Fused scan: per-block exclusive scan + atomic global block offset.
// CSR ranges land in block-arrival order — any disjoint partition is valid.
__global__ __launch_bounds__(256) void scan_fused_kernel() {
    __shared__ int s[256];
    __shared__ int base;
    int t = threadIdx.x;
    int i = blockIdx.x * 256 + t;
    int c = (i < N_NODES) ? g_cnt[i] : 0;
    s[t] = c;
    __syncthreads();
    for (int o = 1; o < 256; o <<= 1) {
        int v = (t >= o) ? s[t - o] : 0;
        __syncthreads();
        s[t] += v;
        __syncthreads();
    }
    if (t == 255) base = atomicAdd(&g_total, s[255]);
    __syncthreads();
    if (i < N_NODES) {
        int rp = base + s[t] - c;
        g_rp[i] = rp;
        g_cur[i] = rp;
        g_deg[i] = (float)c;
    }
}

__global__ __launch_bounds__(256) void fill_kernel(const void* __restrict__ ei) {
    int e = blockIdx.x * blockDim.x + threadIdx.x;
    if (e >= N_EDGES) return;
    bool is64 = (g_any == 0);
    int src, dst;
    load_edge(ei, e, is64, src, dst);
    int p = atomicAdd(&g_cur[dst], 1);
    g_srcs[p] = src;
}

// ---------------- pull layer 1: 16 threads per dst, 64 ch as float4 ----------
__global__ __launch_bounds__(256) void pull1_kernel(const float* __restrict__ x) {
    int tid = blockIdx.x * blockDim.x + threadIdx.x;
    int d = tid >> 4, c = tid & 15;
    if (d >= N_NODES) return;
    int beg = g_rp[d];
    int end = beg + g_cnt[d];
    float4 acc = make_float4(0.f, 0.f, 0.f, 0.f);
#pragma unroll 4
    for (int j = beg; j < end; j++) {
        int s = __ldg(&g_srcs[j]);
        float4 v = __ldg((const float4*)x + s * (IN_C / 4) + c);
        acc.x += v.x; acc.y += v.y; acc.z += v.z; acc.w += v.w;
    }
    ((float4*)g_Sx)[d * (IN_C / 4) + c] = acc;
}

// ---------------- pull layer 2 on z: Szz[d] = z[d] + sum_src z[src] ----------
__global__ __launch_bounds__(256) void pull2z_kernel() {
    int tid = blockIdx.x * blockDim.x + threadIdx.x;
    int d = tid >> 4, c = tid & 15;
    if (d >= N_NODES) return;
    int beg = g_rp[d];
    int end = beg + g_cnt[d];
    float4 acc = __ldg((const float4*)g_z + d * (OUT_C / 4) + c);  // self
#pragma unroll 4
    for (int j = beg; j < end; j++) {
        int s = __ldg(&g_srcs[j]);
        float4 v = __ldg((const float4*)g_z + s * (OUT_C / 4) + c);
        acc.x += v.x; acc.y += v.y; acc.z += v.z; acc.w += v.w;
    }
    ((float4*)g_Szz)[d * (OUT_C / 4) + c] = acc;
}

// ==================== dense layer 1 (8 nodes x 2 cols per warp) — unchanged ====
// h = relu( v @ W1 + degp1*b1 ), v = [degp1*x (64), Sx+x (64), se (1)]
#define D1_N 32
__global__ __launch_bounds__(256) void dense1_kernel(
    const float* __restrict__ x, const float* __restrict__ W1,
    const float* __restrict__ b1) {
    extern __shared__ float sm[];
    ull*   Wp = (ull*)sm;                 // 64 pair-rows x 128 cols (64KB)
    float* vp = (float*)(Wp + 8192);      // 32 nodes x 128 floats (16KB)
    float* bs = vp + 32 * 128;            // 128
    float* we = bs + 128;                 // 128 (W1 row 128)
    float* dg = we + 128;                 // 32
    float* sep = dg + 32;                 // 32
    int tid = threadIdx.x;
    int warp = tid >> 5, lane = tid & 31;
    int ng = warp >> 1;
    int j2 = (warp & 1) * 64 + lane * 2;
    for (int i = tid; i < 8192; i += 256) {
        int p = i >> 7, j = i & 127;
        Wp[i] = f2ull(W1[(2 * p) * 128 + j], W1[(2 * p + 1) * 128 + j]);
    }
    if (tid < 128) { bs[tid] = b1[tid]; we[tid] = W1[128 * 128 + tid]; }

    int iters = (N_NODES + D1_N - 1) / D1_N;
    for (int it = blockIdx.x; it < iters; it += gridDim.x) {
        int base = it * D1_N;
        __syncthreads();
        if (tid < D1_N) {
            int gn = base + tid;
            bool ok = gn < N_NODES;
            dg[tid]  = ok ? g_deg[gn] + 1.0f : 1.0f;
            sep[tid] = ok ? g_se[gn] : 0.0f;
        }
        __syncthreads();
        for (int idx = tid; idx < D1_N * 64; idx += 256) {
            int n = idx >> 6, k = idx & 63;
            int gn = base + n;
            float xv = 0.f, sv = 0.f;
            if (gn < N_NODES) { xv = x[gn * 64 + k]; sv = g_Sx[gn * 64 + k]; }
            vp[n * 128 + k]      = dg[n] * xv;
            vp[n * 128 + 64 + k] = sv + xv;
        }
        __syncthreads();

        ull acc[8][2];
#pragma unroll
        for (int n = 0; n < 8; n++) { acc[n][0] = 0ull; acc[n][1] = 0ull; }
        const float* v0 = vp + (ng * 8) * 128;
#pragma unroll 2
        for (int p = 0; p < 64; p += 2) {
            ulonglong2 w0 = *(const ulonglong2*)&Wp[p * 128 + j2];
            ulonglong2 w1 = *(const ulonglong2*)&Wp[(p + 1) * 128 + j2];
#pragma unroll
            for (int n = 0; n < 8; n++) {
                ulonglong2 vv = *(const ulonglong2*)(v0 + n * 128 + 2 * p);
                ffma2(acc[n][0], w0.x, vv.x);
                ffma2(acc[n][1], w0.y, vv.x);
                ffma2(acc[n][0], w1.x, vv.y);
                ffma2(acc[n][1], w1.y, vv.y);
            }
        }
        float b0 = bs[j2], b1v = bs[j2 + 1];
        float we0 = we[j2], we1 = we[j2 + 1];
#pragma unroll
        for (int n = 0; n < 8; n++) {
            int ln = ng * 8 + n;
            int gn = base + ln;
            if (gn < N_NODES) {
                float d = dg[ln], se = sep[ln];
                float2 r;
                r.x = fmaxf(pairsum(acc[n][0]) + fmaf(d, b0,  se * we0), 0.f);
                r.y = fmaxf(pairsum(acc[n][1]) + fmaf(d, b1v, se * we1), 0.f);
                *(float2*)&g_h[gn * 128 + j2] = r;
            }
        }
    }
}

// ==================== zmm: z = h @ Wj2 (W2 rows 128..255), 8n x 2c per warp ==
#define DZ_N 32
__global__ __launch_bounds__(128) void zmm_kernel(const float* __restrict__ W2) {
    extern __shared__ float sm[];
    ull*   Wp = (ull*)sm;                 // 64 pair-rows x 64 cols (32KB)
    float* vp = (float*)(Wp + 4096);      // 32 nodes x 128 floats (16KB)
    int tid = threadIdx.x;
    int warp = tid >> 5, lane = tid & 31;
    int j2 = lane * 2;
    for (int i = tid; i < 4096; i += 128) {
        int p = i >> 6, j = i & 63;
        Wp[i] = f2ull(W2[(128 + 2 * p) * 64 + j], W2[(128 + 2 * p + 1) * 64 + j]);
    }

    int iters = (N_NODES + DZ_N - 1) / DZ_N;
    for (int it = blockIdx.x; it < iters; it += gridDim.x) {
        int base = it * DZ_N;
        __syncthreads();
        for (int idx = tid; idx < DZ_N * 64; idx += 128) {
            int n = idx >> 6, kk = idx & 63;   // k = 2*kk
            int gn = base + n;
            float2 hv = make_float2(0.f, 0.f);
            if (gn < N_NODES) hv = *(const float2*)&g_h[gn * 128 + 2 * kk];
            *(float2*)&vp[n * 128 + 2 * kk] = hv;
        }
        __syncthreads();

        ull acc[8][2];
#pragma unroll
        for (int n = 0; n < 8; n++) { acc[n][0] = 0ull; acc[n][1] = 0ull; }
        const float* v0 = vp + (warp * 8) * 128;
#pragma unroll 2
        for (int p = 0; p < 64; p += 2) {
            ulonglong2 w0 = *(const ulonglong2*)&Wp[p * 64 + j2];
            ulonglong2 w1 = *(const ulonglong2*)&Wp[(p + 1) * 64 + j2];
#pragma unroll
            for (int n = 0; n < 8; n++) {
                ulonglong2 vv = *(const ulonglong2*)(v0 + n * 128 + 2 * p);
                ffma2(acc[n][0], w0.x, vv.x);
                ffma2(acc[n][1], w0.y, vv.x);
                ffma2(acc[n][0], w1.x, vv.y);
                ffma2(acc[n][1], w1.y, vv.y);
            }
        }
#pragma unroll
        for (int n = 0; n < 8; n++) {
            int gn = base + warp * 8 + n;
            if (gn < N_NODES) {
                float2 r = make_float2(pairsum(acc[n][0]), pairsum(acc[n][1]));
                *(float2*)&g_z[gn * 64 + j2] = r;
            }
        }
    }
}

// ==================== dense layer 2' (K=128) + fused relu & log_softmax =======
// out = log_softmax( relu( degp1*(h@Wi2 + b2) + Szz + se*We2 ) )
#define D2_N 32
__global__ __launch_bounds__(128) void dense2_kernel(
    const float* __restrict__ W2, const float* __restrict__ b2,
    float* __restrict__ out) {
    extern __shared__ float sm[];
    ull*   Wp = (ull*)sm;                 // 64 pair-rows x 64 cols (32KB, Wi2)
    float* vp = (float*)(Wp + 4096);      // 32 nodes x 128 floats (16KB)
    float* bs = vp + 32 * 128;            // 64
    float* we = bs + 64;                  // 64 (W2 row 256)
    float* dg = we + 64;                  // 32
    float* sep = dg + 32;                 // 32
    int tid = threadIdx.x;
    int warp = tid >> 5, lane = tid & 31;
    int j2 = lane * 2;
    for (int i = tid; i < 4096; i += 128) {
        int p = i >> 6, j = i & 63;
        Wp[i] = f2ull(W2[(2 * p) * 64 + j], W2[(2 * p + 1) * 64 + j]);
    }
    if (tid < 64) { bs[tid] = b2[tid]; we[tid] = W2[256 * 64 + tid]; }

    int iters = (N_NODES + D2_N - 1) / D2_N;
    for (int it = blockIdx.x; it < iters; it += gridDim.x) {
        int base = it * D2_N;
        __syncthreads();
        if (tid < D2_N) {
            int gn = base + tid;
            bool ok = gn < N_NODES;
            dg[tid]  = ok ? g_deg[gn] + 1.0f : 1.0f;
            sep[tid] = ok ? g_se[gn] : 0.0f;
        }
        __syncthreads();
        for (int idx = tid; idx < D2_N * 64; idx += 128) {
            int n = idx >> 6, kk = idx & 63;   // k = 2*kk
            int gn = base + n;
            float2 hv = make_float2(0.f, 0.f);
            if (gn < N_NODES) hv = *(const float2*)&g_h[gn * 128 + 2 * kk];
            float d = dg[n];
            *(float2*)&vp[n * 128 + 2 * kk] = make_float2(d * hv.x, d * hv.y);
        }
        __syncthreads();

        ull acc[8][2];
#pragma unroll
        for (int n = 0; n < 8; n++) { acc[n][0] = 0ull; acc[n][1] = 0ull; }
        const float* v0 = vp + (warp * 8) * 128;
#pragma unroll 2
        for (int p = 0; p < 64; p += 2) {
            ulonglong2 w0 = *(const ulonglong2*)&Wp[p * 64 + j2];
            ulonglong2 w1 = *(const ulonglong2*)&Wp[(p + 1) * 64 + j2];
#pragma unroll
            for (int n = 0; n < 8; n++) {
                ulonglong2 vv = *(const ulonglong2*)(v0 + n * 128 + 2 * p);
                ffma2(acc[n][0], w0.x, vv.x);
                ffma2(acc[n][1], w0.y, vv.x);
                ffma2(acc[n][0], w1.x, vv.y);
                ffma2(acc[n][1], w1.y, vv.y);
            }
        }

        float bx = bs[j2], by = bs[j2 + 1];
        float wex = we[j2], wey = we[j2 + 1];
#pragma unroll
        for (int n = 0; n < 8; n++) {
            int ln = warp * 8 + n;
            int gn = base + ln;
            float d = dg[ln], se = sep[ln];
            float2 szz = make_float2(0.f, 0.f);
            if (gn < N_NODES) szz = *(const float2*)&g_Szz[gn * 64 + j2];
            float rx = fmaxf(pairsum(acc[n][0]) + fmaf(d, bx, szz.x + se * wex), 0.f);
            float ry = fmaxf(pairsum(acc[n][1]) + fmaf(d, by, szz.y + se * wey), 0.f);
            float m = fmaxf(rx, ry);
#pragma unroll
            for (int o = 16; o; o >>= 1) m = fmaxf(m, __shfl_xor_sync(0xffffffffu, m, o));
            float s = __expf(rx - m) + __expf(ry - m);
#pragma unroll
            for (int o = 16; o; o >>= 1) s += __shfl_xor_sync(0xffffffffu, s, o);
            float ls = __logf(s) + m;
            if (gn < N_NODES) {
                float2 r = make_float2(rx - ls, ry - ls);
                *(float2*)&out[gn * 64 + j2] = r;
            }
        }
    }
}

// ---------------- launch ------------------------------------------------------
extern "C" void kernel_launch(void* const* d_in, const int* in_sizes, int n_in,
                              void* d_out, int out_size) {
    const float* x  = (const float*)d_in[0];
    const void*  ei = d_in[1];
    const float* ea = (const float*)d_in[2];
    const float* W1 = (const float*)d_in[3];
    const float* b1 = (const float*)d_in[4];
    const float* W2 = (const float*)d_in[5];
    const float* b2 = (const float*)d_in[6];
    float* out = (float*)d_out;

    int smem1 = 8192 * 8 + 32 * 128 * 4 + (128 + 128 + 32 + 32) * 4;  // 83,200 B
    int smemz = 4096 * 8 + 32 * 128 * 4;                              // 49,152 B
    int smem2 = 4096 * 8 + 32 * 128 * 4 + (64 + 64 + 32 + 32) * 4;    // 49,920 B
    cudaFuncSetAttribute(dense1_kernel, cudaFuncAttributeMaxDynamicSharedMemorySize, smem1);
    cudaFuncSetAttribute(zmm_kernel,    cudaFuncAttributeMaxDynamicSharedMemorySize, smemz);
    cudaFuncSetAttribute(dense2_kernel, cudaFuncAttributeMaxDynamicSharedMemorySize, smem2);

    zero_kernel<<<256, 256>>>((const int*)ei);
    hist_kernel<<<(N_EDGES + 255) / 256, 256>>>(ei, ea);
    scan_fused_kernel<<<SCAN_BLOCKS, 256>>>();
    fill_kernel<<<(N_EDGES + 255) / 256, 256>>>(ei);
    pull1_kernel<<<(N_NODES * 16 + 255) / 256, 256>>>(x);
    dense1_kernel<<<296, 256, smem1>>>(x, W1, b1);
    zmm_kernel<<<592, 128, smemz>>>(W2);
    pull2z_kernel<<<(N_NODES * 16 + 255) / 256, 256>>>();
    dense2_kernel<<<592, 128, smem2>>>(W2, b2, out);
}